// round 1
// baseline (speedup 1.0000x reference)
#include <cuda_runtime.h>

#define N_NODES 100000
#define N_EDGES 1600000
#define D 128

// Scratch for support = features @ W  (51.2 MB). __device__ global: allowed.
__device__ float g_support[(size_t)N_NODES * D];

// ---------------------------------------------------------------------------
// GEMM: g_support[M,128] = A[M,128] * B[128,128]
// 128x128 CTA tile, BK=8, 256 threads, 8x8 register microtile per thread.
// ---------------------------------------------------------------------------
__global__ __launch_bounds__(256) void gemm_kernel(const float* __restrict__ A,
                                                   const float* __restrict__ B) {
    __shared__ __align__(16) float As[8][128];  // [k][m] (transposed A tile)
    __shared__ __align__(16) float Bs[8][128];  // [k][n]

    const int tid = threadIdx.x;
    const int tx = tid & 15;        // 0..15 -> n microtile
    const int ty = tid >> 4;        // 0..15 -> m microtile
    const int blockM = blockIdx.x * 128;

    // A-tile loader: thread -> (row 0..127, kchunk {0,4}), float4 along k
    const int a_row = tid >> 1;
    const int a_kc  = (tid & 1) * 4;
    // B-tile loader: thread -> (k 0..7, n chunk), float4 along n
    const int b_k = tid >> 5;
    const int b_n = (tid & 31) * 4;

    float acc[8][8];
#pragma unroll
    for (int i = 0; i < 8; i++)
#pragma unroll
        for (int j = 0; j < 8; j++) acc[i][j] = 0.0f;

    for (int k0 = 0; k0 < 128; k0 += 8) {
        // Load A tile (guard M tail), store transposed
        int gr = blockM + a_row;
        float4 av = make_float4(0.f, 0.f, 0.f, 0.f);
        if (gr < N_NODES)
            av = *reinterpret_cast<const float4*>(A + (size_t)gr * D + k0 + a_kc);
        As[a_kc + 0][a_row] = av.x;
        As[a_kc + 1][a_row] = av.y;
        As[a_kc + 2][a_row] = av.z;
        As[a_kc + 3][a_row] = av.w;

        // Load B tile (always in-bounds: B is 128x128)
        *reinterpret_cast<float4*>(&Bs[b_k][b_n]) =
            *reinterpret_cast<const float4*>(B + (size_t)(k0 + b_k) * D + b_n);

        __syncthreads();

#pragma unroll
        for (int k = 0; k < 8; k++) {
            float a[8], b[8];
            *reinterpret_cast<float4*>(&a[0]) = *reinterpret_cast<const float4*>(&As[k][ty * 8]);
            *reinterpret_cast<float4*>(&a[4]) = *reinterpret_cast<const float4*>(&As[k][ty * 8 + 4]);
            *reinterpret_cast<float4*>(&b[0]) = *reinterpret_cast<const float4*>(&Bs[k][tx * 8]);
            *reinterpret_cast<float4*>(&b[4]) = *reinterpret_cast<const float4*>(&Bs[k][tx * 8 + 4]);
#pragma unroll
            for (int i = 0; i < 8; i++)
#pragma unroll
                for (int j = 0; j < 8; j++)
                    acc[i][j] = fmaf(a[i], b[j], acc[i][j]);
        }
        __syncthreads();
    }

#pragma unroll
    for (int i = 0; i < 8; i++) {
        int gr = blockM + ty * 8 + i;
        if (gr < N_NODES) {
            float* cp = g_support + (size_t)gr * D + tx * 8;
            *reinterpret_cast<float4*>(cp)     = *reinterpret_cast<const float4*>(&acc[i][0]);
            *reinterpret_cast<float4*>(cp + 4) = *reinterpret_cast<const float4*>(&acc[i][4]);
        }
    }
}

// ---------------------------------------------------------------------------
// Zero the output accumulator (d_out is poisoned 0xAA by the harness)
// ---------------------------------------------------------------------------
__global__ void zero_kernel(float4* __restrict__ out, int n4) {
    int i = blockIdx.x * blockDim.x + threadIdx.x;
    if (i < n4) out[i] = make_float4(0.f, 0.f, 0.f, 0.f);
}

// ---------------------------------------------------------------------------
// Scatter: warp per edge. out[row] += val * support[col]
// Lane l handles floats [4l, 4l+4). (row,col,val) loads are warp-uniform.
// ---------------------------------------------------------------------------
__global__ __launch_bounds__(256) void scatter_kernel(const float* __restrict__ edge_val,
                                                      const int* __restrict__ edge_row,
                                                      const int* __restrict__ edge_col,
                                                      float* __restrict__ out) {
    int gtid = blockIdx.x * blockDim.x + threadIdx.x;
    int e = gtid >> 5;
    int lane = threadIdx.x & 31;
    if (e >= N_EDGES) return;

    int r = edge_row[e];
    int c = edge_col[e];
    float v = edge_val[e];

    float4 s = *reinterpret_cast<const float4*>(g_support + (size_t)c * D + lane * 4);
    float* o = out + (size_t)r * D + lane * 4;
    atomicAdd(o + 0, v * s.x);
    atomicAdd(o + 1, v * s.y);
    atomicAdd(o + 2, v * s.z);
    atomicAdd(o + 3, v * s.w);
}

// ---------------------------------------------------------------------------
// In-place ReLU
// ---------------------------------------------------------------------------
__global__ void relu_kernel(float4* __restrict__ out, int n4) {
    int i = blockIdx.x * blockDim.x + threadIdx.x;
    if (i < n4) {
        float4 v = out[i];
        v.x = fmaxf(v.x, 0.f);
        v.y = fmaxf(v.y, 0.f);
        v.z = fmaxf(v.z, 0.f);
        v.w = fmaxf(v.w, 0.f);
        out[i] = v;
    }
}

extern "C" void kernel_launch(void* const* d_in, const int* in_sizes, int n_in,
                              void* d_out, int out_size) {
    const float* features = (const float*)d_in[0];   // [100000, 128]
    const float* weight   = (const float*)d_in[1];   // [128, 128]
    const float* edge_val = (const float*)d_in[2];   // [1600000]
    const int*   edge_row = (const int*)d_in[3];     // [1600000]
    const int*   edge_col = (const int*)d_in[4];     // [1600000]
    float* out = (float*)d_out;                      // [100000, 128]

    const int n4 = (N_NODES * D) / 4;  // 3,200,000

    // 1) support = features @ W
    gemm_kernel<<<(N_NODES + 127) / 128, 256>>>(features, weight);

    // 2) out = 0
    zero_kernel<<<(n4 + 255) / 256, 256>>>((float4*)out, n4);

    // 3) scatter-add: out[row] += val * support[col]
    {
        long long threads = (long long)N_EDGES * 32;
        int blocks = (int)((threads + 255) / 256);
        scatter_kernel<<<blocks, 256>>>(edge_val, edge_row, edge_col, out);
    }

    // 4) relu in place
    relu_kernel<<<(n4 + 255) / 256, 256>>>((float4*)out, n4);
}

// round 2
// speedup vs baseline: 1.7573x; 1.7573x over previous
#include <cuda_runtime.h>

#define N_NODES 100000
#define N_EDGES 1600000
#define D 128

// Scratch for support = features @ W  (51.2 MB). __device__ global: allowed.
__device__ float g_support[(size_t)N_NODES * D];

// ---------------------------------------------------------------------------
// GEMM: g_support[M,128] = A[M,128] * B[128,128]
// 128x128 CTA tile, BK=8, 256 threads, 8x8 register microtile per thread.
// ---------------------------------------------------------------------------
__global__ __launch_bounds__(256) void gemm_kernel(const float* __restrict__ A,
                                                   const float* __restrict__ B) {
    __shared__ __align__(16) float As[8][128];  // [k][m] (transposed A tile)
    __shared__ __align__(16) float Bs[8][128];  // [k][n]

    const int tid = threadIdx.x;
    const int tx = tid & 15;        // 0..15 -> n microtile
    const int ty = tid >> 4;        // 0..15 -> m microtile
    const int blockM = blockIdx.x * 128;

    const int a_row = tid >> 1;
    const int a_kc  = (tid & 1) * 4;
    const int b_k = tid >> 5;
    const int b_n = (tid & 31) * 4;

    float acc[8][8];
#pragma unroll
    for (int i = 0; i < 8; i++)
#pragma unroll
        for (int j = 0; j < 8; j++) acc[i][j] = 0.0f;

    for (int k0 = 0; k0 < 128; k0 += 8) {
        int gr = blockM + a_row;
        float4 av = make_float4(0.f, 0.f, 0.f, 0.f);
        if (gr < N_NODES)
            av = *reinterpret_cast<const float4*>(A + (size_t)gr * D + k0 + a_kc);
        As[a_kc + 0][a_row] = av.x;
        As[a_kc + 1][a_row] = av.y;
        As[a_kc + 2][a_row] = av.z;
        As[a_kc + 3][a_row] = av.w;

        *reinterpret_cast<float4*>(&Bs[b_k][b_n]) =
            *reinterpret_cast<const float4*>(B + (size_t)(k0 + b_k) * D + b_n);

        __syncthreads();

#pragma unroll
        for (int k = 0; k < 8; k++) {
            float a[8], b[8];
            *reinterpret_cast<float4*>(&a[0]) = *reinterpret_cast<const float4*>(&As[k][ty * 8]);
            *reinterpret_cast<float4*>(&a[4]) = *reinterpret_cast<const float4*>(&As[k][ty * 8 + 4]);
            *reinterpret_cast<float4*>(&b[0]) = *reinterpret_cast<const float4*>(&Bs[k][tx * 8]);
            *reinterpret_cast<float4*>(&b[4]) = *reinterpret_cast<const float4*>(&Bs[k][tx * 8 + 4]);
#pragma unroll
            for (int i = 0; i < 8; i++)
#pragma unroll
                for (int j = 0; j < 8; j++)
                    acc[i][j] = fmaf(a[i], b[j], acc[i][j]);
        }
        __syncthreads();
    }

#pragma unroll
    for (int i = 0; i < 8; i++) {
        int gr = blockM + ty * 8 + i;
        if (gr < N_NODES) {
            float* cp = g_support + (size_t)gr * D + tx * 8;
            *reinterpret_cast<float4*>(cp)     = *reinterpret_cast<const float4*>(&acc[i][0]);
            *reinterpret_cast<float4*>(cp + 4) = *reinterpret_cast<const float4*>(&acc[i][4]);
        }
    }
}

// ---------------------------------------------------------------------------
// Zero the output accumulator (d_out is poisoned 0xAA by the harness)
// ---------------------------------------------------------------------------
__global__ void zero_kernel(float4* __restrict__ out, int n4) {
    int i = blockIdx.x * blockDim.x + threadIdx.x;
    if (i < n4) out[i] = make_float4(0.f, 0.f, 0.f, 0.f);
}

// ---------------------------------------------------------------------------
// Scatter: warp per edge. out[row] += val * support[col]
// Lane l handles floats [4l, 4l+4) -> ONE red.global.add.v4.f32 per lane.
// ---------------------------------------------------------------------------
__device__ __forceinline__ void red_add_v4(float* addr, float x, float y, float z, float w) {
    asm volatile("red.global.add.v4.f32 [%0], {%1, %2, %3, %4};"
                 :: "l"(addr), "f"(x), "f"(y), "f"(z), "f"(w)
                 : "memory");
}

__global__ __launch_bounds__(256) void scatter_kernel(const float* __restrict__ edge_val,
                                                      const int* __restrict__ edge_row,
                                                      const int* __restrict__ edge_col,
                                                      float* __restrict__ out) {
    int gtid = blockIdx.x * blockDim.x + threadIdx.x;
    int e = gtid >> 5;
    int lane = threadIdx.x & 31;
    if (e >= N_EDGES) return;

    int r = edge_row[e];
    int c = edge_col[e];
    float v = edge_val[e];

    float4 s = *reinterpret_cast<const float4*>(g_support + (size_t)c * D + lane * 4);
    float* o = out + (size_t)r * D + lane * 4;
    red_add_v4(o, v * s.x, v * s.y, v * s.z, v * s.w);
}

// ---------------------------------------------------------------------------
// In-place ReLU
// ---------------------------------------------------------------------------
__global__ void relu_kernel(float4* __restrict__ out, int n4) {
    int i = blockIdx.x * blockDim.x + threadIdx.x;
    if (i < n4) {
        float4 v = out[i];
        v.x = fmaxf(v.x, 0.f);
        v.y = fmaxf(v.y, 0.f);
        v.z = fmaxf(v.z, 0.f);
        v.w = fmaxf(v.w, 0.f);
        out[i] = v;
    }
}

extern "C" void kernel_launch(void* const* d_in, const int* in_sizes, int n_in,
                              void* d_out, int out_size) {
    const float* features = (const float*)d_in[0];   // [100000, 128]
    const float* weight   = (const float*)d_in[1];   // [128, 128]
    const float* edge_val = (const float*)d_in[2];   // [1600000]
    const int*   edge_row = (const int*)d_in[3];     // [1600000]
    const int*   edge_col = (const int*)d_in[4];     // [1600000]
    float* out = (float*)d_out;                      // [100000, 128]

    const int n4 = (N_NODES * D) / 4;  // 3,200,000

    // 1) support = features @ W
    gemm_kernel<<<(N_NODES + 127) / 128, 256>>>(features, weight);

    // 2) out = 0
    zero_kernel<<<(n4 + 255) / 256, 256>>>((float4*)out, n4);

    // 3) scatter-add: out[row] += val * support[col]   (vector RED)
    {
        long long threads = (long long)N_EDGES * 32;
        int blocks = (int)((threads + 255) / 256);
        scatter_kernel<<<blocks, 256>>>(edge_val, edge_row, edge_col, out);
    }

    // 4) relu in place
    relu_kernel<<<(n4 + 255) / 256, 256>>>((float4*)out, n4);
}

// round 3
// speedup vs baseline: 2.0562x; 1.1700x over previous
#include <cuda_runtime.h>

#define N_NODES 100000
#define N_EDGES 1600000
#define D 128

// Device scratch (allocation-rule-compliant __device__ globals)
__device__ float g_support[(size_t)N_NODES * D];        // 51.2 MB
__device__ int   g_count[N_NODES];                      // histogram
__device__ int   g_cursor[N_NODES];                     // fill cursors
__device__ int   g_rowstart[N_NODES + 1];               // CSR offsets
__device__ int   g_csr_col[N_EDGES];                    // 6.4 MB
__device__ float g_csr_val[N_EDGES];                    // 6.4 MB

// ---------------------------------------------------------------------------
// GEMM: g_support[M,128] = A[M,128] * B[128,128]
// 128x128 CTA tile, BK=8, 256 threads, 8x8 register microtile per thread.
// ---------------------------------------------------------------------------
__global__ __launch_bounds__(256) void gemm_kernel(const float* __restrict__ A,
                                                   const float* __restrict__ B) {
    __shared__ __align__(16) float As[8][128];  // [k][m]
    __shared__ __align__(16) float Bs[8][128];  // [k][n]

    const int tid = threadIdx.x;
    const int tx = tid & 15;
    const int ty = tid >> 4;
    const int blockM = blockIdx.x * 128;

    const int a_row = tid >> 1;
    const int a_kc  = (tid & 1) * 4;
    const int b_k = tid >> 5;
    const int b_n = (tid & 31) * 4;

    float acc[8][8];
#pragma unroll
    for (int i = 0; i < 8; i++)
#pragma unroll
        for (int j = 0; j < 8; j++) acc[i][j] = 0.0f;

    for (int k0 = 0; k0 < 128; k0 += 8) {
        int gr = blockM + a_row;
        float4 av = make_float4(0.f, 0.f, 0.f, 0.f);
        if (gr < N_NODES)
            av = *reinterpret_cast<const float4*>(A + (size_t)gr * D + k0 + a_kc);
        As[a_kc + 0][a_row] = av.x;
        As[a_kc + 1][a_row] = av.y;
        As[a_kc + 2][a_row] = av.z;
        As[a_kc + 3][a_row] = av.w;

        *reinterpret_cast<float4*>(&Bs[b_k][b_n]) =
            *reinterpret_cast<const float4*>(B + (size_t)(k0 + b_k) * D + b_n);

        __syncthreads();

#pragma unroll
        for (int k = 0; k < 8; k++) {
            float a[8], b[8];
            *reinterpret_cast<float4*>(&a[0]) = *reinterpret_cast<const float4*>(&As[k][ty * 8]);
            *reinterpret_cast<float4*>(&a[4]) = *reinterpret_cast<const float4*>(&As[k][ty * 8 + 4]);
            *reinterpret_cast<float4*>(&b[0]) = *reinterpret_cast<const float4*>(&Bs[k][tx * 8]);
            *reinterpret_cast<float4*>(&b[4]) = *reinterpret_cast<const float4*>(&Bs[k][tx * 8 + 4]);
#pragma unroll
            for (int i = 0; i < 8; i++)
#pragma unroll
                for (int j = 0; j < 8; j++)
                    acc[i][j] = fmaf(a[i], b[j], acc[i][j]);
        }
        __syncthreads();
    }

#pragma unroll
    for (int i = 0; i < 8; i++) {
        int gr = blockM + ty * 8 + i;
        if (gr < N_NODES) {
            float* cp = g_support + (size_t)gr * D + tx * 8;
            *reinterpret_cast<float4*>(cp)     = *reinterpret_cast<const float4*>(&acc[i][0]);
            *reinterpret_cast<float4*>(cp + 4) = *reinterpret_cast<const float4*>(&acc[i][4]);
        }
    }
}

// ---------------------------------------------------------------------------
// CSR build step 1: zero histogram + cursors
// ---------------------------------------------------------------------------
__global__ void zero_counts_kernel() {
    int i = blockIdx.x * blockDim.x + threadIdx.x;
    if (i < N_NODES) {
        g_count[i] = 0;
        g_cursor[i] = 0;
    }
}

// step 2: histogram of edge_row
__global__ void hist_kernel(const int* __restrict__ edge_row) {
    int e = blockIdx.x * blockDim.x + threadIdx.x;
    if (e < N_EDGES) atomicAdd(&g_count[edge_row[e]], 1);
}

// step 3: exclusive prefix sum over g_count -> g_rowstart (single CTA, tiled)
__global__ __launch_bounds__(1024) void scan_kernel() {
    __shared__ int warp_sums[32];
    __shared__ int carry_s;
    const int tid = threadIdx.x;
    const int lane = tid & 31;
    const int wid = tid >> 5;
    int carry = 0;

    for (int base = 0; base < N_NODES; base += 1024) {
        int i = base + tid;
        int x = (i < N_NODES) ? g_count[i] : 0;
        int v = x;
#pragma unroll
        for (int o = 1; o < 32; o <<= 1) {
            int t = __shfl_up_sync(0xFFFFFFFFu, v, o);
            if (lane >= o) v += t;
        }
        if (lane == 31) warp_sums[wid] = v;
        __syncthreads();
        if (tid < 32) {
            int w = warp_sums[tid];
#pragma unroll
            for (int o = 1; o < 32; o <<= 1) {
                int t = __shfl_up_sync(0xFFFFFFFFu, w, o);
                if (tid >= o) w += t;
            }
            warp_sums[tid] = w;
        }
        __syncthreads();
        int incl = v + (wid > 0 ? warp_sums[wid - 1] : 0);
        if (i < N_NODES) g_rowstart[i] = carry + incl - x;  // exclusive
        if (tid == 1023) carry_s = carry + incl;            // tile total
        __syncthreads();
        carry = carry_s;
    }
    if (tid == 0) g_rowstart[N_NODES] = carry;  // == N_EDGES
}

// step 4: fill CSR (col, val) pairs
__global__ void fill_kernel(const float* __restrict__ edge_val,
                            const int* __restrict__ edge_row,
                            const int* __restrict__ edge_col) {
    int e = blockIdx.x * blockDim.x + threadIdx.x;
    if (e < N_EDGES) {
        int r = edge_row[e];
        int p = g_rowstart[r] + atomicAdd(&g_cursor[r], 1);
        g_csr_col[p] = edge_col[e];
        g_csr_val[p] = edge_val[e];
    }
}

// ---------------------------------------------------------------------------
// Gather: one warp per output row. acc = sum(val * support[col]); ReLU; store.
// Lane l owns floats [4l, 4l+4). No atomics, no zero pass, no relu pass.
// ---------------------------------------------------------------------------
__global__ __launch_bounds__(256) void gather_kernel(float* __restrict__ out) {
    int row = blockIdx.x * 8 + (threadIdx.x >> 5);
    int lane = threadIdx.x & 31;
    if (row >= N_NODES) return;

    int s = g_rowstart[row];
    int e = g_rowstart[row + 1];

    float4 acc = make_float4(0.f, 0.f, 0.f, 0.f);
#pragma unroll 4
    for (int i = s; i < e; i++) {
        int c = g_csr_col[i];       // warp-uniform (L1 broadcast)
        float v = g_csr_val[i];
        float4 sv = *reinterpret_cast<const float4*>(g_support + (size_t)c * D + lane * 4);
        acc.x = fmaf(v, sv.x, acc.x);
        acc.y = fmaf(v, sv.y, acc.y);
        acc.z = fmaf(v, sv.z, acc.z);
        acc.w = fmaf(v, sv.w, acc.w);
    }

    acc.x = fmaxf(acc.x, 0.f);
    acc.y = fmaxf(acc.y, 0.f);
    acc.z = fmaxf(acc.z, 0.f);
    acc.w = fmaxf(acc.w, 0.f);
    *reinterpret_cast<float4*>(out + (size_t)row * D + lane * 4) = acc;
}

extern "C" void kernel_launch(void* const* d_in, const int* in_sizes, int n_in,
                              void* d_out, int out_size) {
    const float* features = (const float*)d_in[0];   // [100000, 128]
    const float* weight   = (const float*)d_in[1];   // [128, 128]
    const float* edge_val = (const float*)d_in[2];   // [1600000]
    const int*   edge_row = (const int*)d_in[3];     // [1600000]
    const int*   edge_col = (const int*)d_in[4];     // [1600000]
    float* out = (float*)d_out;                      // [100000, 128]

    // 1) support = features @ W
    gemm_kernel<<<(N_NODES + 127) / 128, 256>>>(features, weight);

    // 2) CSR build (overlaps nothing, but cheap)
    zero_counts_kernel<<<(N_NODES + 255) / 256, 256>>>();
    hist_kernel<<<(N_EDGES + 255) / 256, 256>>>(edge_row);
    scan_kernel<<<1, 1024>>>();
    fill_kernel<<<(N_EDGES + 255) / 256, 256>>>(edge_val, edge_row, edge_col);

    // 3) fused gather + ReLU -> out
    gather_kernel<<<(N_NODES + 7) / 8, 256>>>(out);
}

// round 4
// speedup vs baseline: 2.6781x; 1.3025x over previous
#include <cuda_runtime.h>

#define N_NODES 100000
#define N_EDGES 1600000
#define D 128
#define SCAN_BLK 1024
#define N_SCAN_BLOCKS ((N_NODES + SCAN_BLK - 1) / SCAN_BLK)   // 98

// Device scratch (allocation-rule-compliant __device__ globals)
__device__ float g_support[(size_t)N_NODES * D];        // 51.2 MB
__device__ int   g_count[N_NODES];                      // histogram
__device__ int   g_cursor[N_NODES];                     // fill cursors
__device__ int   g_rowstart[N_NODES + 1];               // CSR offsets
__device__ int   g_blocksum[N_SCAN_BLOCKS];             // scan partials
__device__ int   g_csr_col[N_EDGES];                    // 6.4 MB
__device__ float g_csr_val[N_EDGES];                    // 6.4 MB

// ---------------------------------------------------------------------------
// GEMM: g_support[M,128] = A[M,128] * B[128,128]
// ---------------------------------------------------------------------------
__global__ __launch_bounds__(256) void gemm_kernel(const float* __restrict__ A,
                                                   const float* __restrict__ B) {
    __shared__ __align__(16) float As[8][128];  // [k][m]
    __shared__ __align__(16) float Bs[8][128];  // [k][n]

    const int tid = threadIdx.x;
    const int tx = tid & 15;
    const int ty = tid >> 4;
    const int blockM = blockIdx.x * 128;

    const int a_row = tid >> 1;
    const int a_kc  = (tid & 1) * 4;
    const int b_k = tid >> 5;
    const int b_n = (tid & 31) * 4;

    float acc[8][8];
#pragma unroll
    for (int i = 0; i < 8; i++)
#pragma unroll
        for (int j = 0; j < 8; j++) acc[i][j] = 0.0f;

    for (int k0 = 0; k0 < 128; k0 += 8) {
        int gr = blockM + a_row;
        float4 av = make_float4(0.f, 0.f, 0.f, 0.f);
        if (gr < N_NODES)
            av = *reinterpret_cast<const float4*>(A + (size_t)gr * D + k0 + a_kc);
        As[a_kc + 0][a_row] = av.x;
        As[a_kc + 1][a_row] = av.y;
        As[a_kc + 2][a_row] = av.z;
        As[a_kc + 3][a_row] = av.w;

        *reinterpret_cast<float4*>(&Bs[b_k][b_n]) =
            *reinterpret_cast<const float4*>(B + (size_t)(k0 + b_k) * D + b_n);

        __syncthreads();

#pragma unroll
        for (int k = 0; k < 8; k++) {
            float a[8], b[8];
            *reinterpret_cast<float4*>(&a[0]) = *reinterpret_cast<const float4*>(&As[k][ty * 8]);
            *reinterpret_cast<float4*>(&a[4]) = *reinterpret_cast<const float4*>(&As[k][ty * 8 + 4]);
            *reinterpret_cast<float4*>(&b[0]) = *reinterpret_cast<const float4*>(&Bs[k][tx * 8]);
            *reinterpret_cast<float4*>(&b[4]) = *reinterpret_cast<const float4*>(&Bs[k][tx * 8 + 4]);
#pragma unroll
            for (int i = 0; i < 8; i++)
#pragma unroll
                for (int j = 0; j < 8; j++)
                    acc[i][j] = fmaf(a[i], b[j], acc[i][j]);
        }
        __syncthreads();
    }

#pragma unroll
    for (int i = 0; i < 8; i++) {
        int gr = blockM + ty * 8 + i;
        if (gr < N_NODES) {
            float* cp = g_support + (size_t)gr * D + tx * 8;
            *reinterpret_cast<float4*>(cp)     = *reinterpret_cast<const float4*>(&acc[i][0]);
            *reinterpret_cast<float4*>(cp + 4) = *reinterpret_cast<const float4*>(&acc[i][4]);
        }
    }
}

// ---------------------------------------------------------------------------
// CSR build
// ---------------------------------------------------------------------------
__global__ void zero_counts_kernel() {
    int i = blockIdx.x * blockDim.x + threadIdx.x;
    if (i < N_NODES) {
        g_count[i] = 0;
        g_cursor[i] = 0;
    }
}

__global__ void hist_kernel(const int* __restrict__ edge_row) {
    int e = blockIdx.x * blockDim.x + threadIdx.x;
    if (e < N_EDGES) atomicAdd(&g_count[edge_row[e]], 1);
}

// Phase 1: per-block exclusive scan of g_count tile -> g_rowstart; block total -> g_blocksum
__global__ __launch_bounds__(SCAN_BLK) void scan_local_kernel() {
    __shared__ int warp_sums[32];
    const int tid = threadIdx.x;
    const int lane = tid & 31;
    const int wid = tid >> 5;
    const int i = blockIdx.x * SCAN_BLK + tid;

    int x = (i < N_NODES) ? g_count[i] : 0;
    int v = x;
#pragma unroll
    for (int o = 1; o < 32; o <<= 1) {
        int t = __shfl_up_sync(0xFFFFFFFFu, v, o);
        if (lane >= o) v += t;
    }
    if (lane == 31) warp_sums[wid] = v;
    __syncthreads();
    if (tid < 32) {
        int w = warp_sums[tid];
#pragma unroll
        for (int o = 1; o < 32; o <<= 1) {
            int t = __shfl_up_sync(0xFFFFFFFFu, w, o);
            if (tid >= o) w += t;
        }
        warp_sums[tid] = w;
    }
    __syncthreads();
    int incl = v + (wid > 0 ? warp_sums[wid - 1] : 0);
    if (i < N_NODES) g_rowstart[i] = incl - x;   // block-local exclusive
    if (tid == SCAN_BLK - 1) g_blocksum[blockIdx.x] = incl;
}

// Phase 2: exclusive scan of the 98 block sums (1 CTA, <=1024 blocks supported)
__global__ __launch_bounds__(128) void scan_blocks_kernel() {
    __shared__ int warp_sums[4];
    const int tid = threadIdx.x;
    const int lane = tid & 31;
    const int wid = tid >> 5;
    int x = (tid < N_SCAN_BLOCKS) ? g_blocksum[tid] : 0;
    int v = x;
#pragma unroll
    for (int o = 1; o < 32; o <<= 1) {
        int t = __shfl_up_sync(0xFFFFFFFFu, v, o);
        if (lane >= o) v += t;
    }
    if (lane == 31) warp_sums[wid] = v;
    __syncthreads();
    if (tid < 4) {
        int w = warp_sums[tid];
#pragma unroll
        for (int o = 1; o < 4; o <<= 1) {
            int t = __shfl_up_sync(0xFu, w, o);
            if (tid >= o) w += t;
        }
        warp_sums[tid] = w;
    }
    __syncthreads();
    int incl = v + (wid > 0 ? warp_sums[wid - 1] : 0);
    if (tid < N_SCAN_BLOCKS) g_blocksum[tid] = incl - x;  // exclusive block offset
    if (tid == N_SCAN_BLOCKS - 1) g_rowstart[N_NODES] = incl;  // total == N_EDGES
}

// Phase 3: add block offsets
__global__ __launch_bounds__(SCAN_BLK) void scan_addoff_kernel() {
    const int i = blockIdx.x * SCAN_BLK + threadIdx.x;
    if (i < N_NODES) g_rowstart[i] += g_blocksum[blockIdx.x];
}

// Fill CSR (col, val) pairs
__global__ void fill_kernel(const float* __restrict__ edge_val,
                            const int* __restrict__ edge_row,
                            const int* __restrict__ edge_col) {
    int e = blockIdx.x * blockDim.x + threadIdx.x;
    if (e < N_EDGES) {
        int r = edge_row[e];
        int p = g_rowstart[r] + atomicAdd(&g_cursor[r], 1);
        g_csr_col[p] = edge_col[e];
        g_csr_val[p] = edge_val[e];
    }
}

// ---------------------------------------------------------------------------
// Gather: one warp per output row. acc = sum(val * support[col]); ReLU; store.
// ---------------------------------------------------------------------------
__global__ __launch_bounds__(256) void gather_kernel(float* __restrict__ out) {
    int row = blockIdx.x * 8 + (threadIdx.x >> 5);
    int lane = threadIdx.x & 31;
    if (row >= N_NODES) return;

    int s = g_rowstart[row];
    int e = g_rowstart[row + 1];

    float4 acc = make_float4(0.f, 0.f, 0.f, 0.f);
#pragma unroll 4
    for (int i = s; i < e; i++) {
        int c = g_csr_col[i];       // warp-uniform
        float v = g_csr_val[i];
        float4 sv = *reinterpret_cast<const float4*>(g_support + (size_t)c * D + lane * 4);
        acc.x = fmaf(v, sv.x, acc.x);
        acc.y = fmaf(v, sv.y, acc.y);
        acc.z = fmaf(v, sv.z, acc.z);
        acc.w = fmaf(v, sv.w, acc.w);
    }

    acc.x = fmaxf(acc.x, 0.f);
    acc.y = fmaxf(acc.y, 0.f);
    acc.z = fmaxf(acc.z, 0.f);
    acc.w = fmaxf(acc.w, 0.f);
    *reinterpret_cast<float4*>(out + (size_t)row * D + lane * 4) = acc;
}

extern "C" void kernel_launch(void* const* d_in, const int* in_sizes, int n_in,
                              void* d_out, int out_size) {
    const float* features = (const float*)d_in[0];   // [100000, 128]
    const float* weight   = (const float*)d_in[1];   // [128, 128]
    const float* edge_val = (const float*)d_in[2];   // [1600000]
    const int*   edge_row = (const int*)d_in[3];     // [1600000]
    const int*   edge_col = (const int*)d_in[4];     // [1600000]
    float* out = (float*)d_out;                      // [100000, 128]

    // 1) support = features @ W
    gemm_kernel<<<(N_NODES + 127) / 128, 256>>>(features, weight);

    // 2) CSR build with hierarchical scan
    zero_counts_kernel<<<(N_NODES + 255) / 256, 256>>>();
    hist_kernel<<<(N_EDGES + 255) / 256, 256>>>(edge_row);
    scan_local_kernel<<<N_SCAN_BLOCKS, SCAN_BLK>>>();
    scan_blocks_kernel<<<1, 128>>>();
    scan_addoff_kernel<<<N_SCAN_BLOCKS, SCAN_BLK>>>();
    fill_kernel<<<(N_EDGES + 255) / 256, 256>>>(edge_val, edge_row, edge_col);

    // 3) fused gather + ReLU -> out
    gather_kernel<<<(N_NODES + 7) / 8, 256>>>(out);
}